// round 6
// baseline (speedup 1.0000x reference)
#include <cuda_runtime.h>
#include <math.h>

#define B_   32
#define NPTS 2048
#define L_   256
#define BIGF 1e18f
#define EPSF 1e-6f

#define LAMBDA_E_SUM       10.0f
#define LAMBDA_HIT         20.0f
#define LAMBDA_CHAMFER     0.001f
#define LAMBDA_HIT_ENTROPY 0.1f

#define GRID_CH 592           // 148 SMs x occupancy 4 -> one wave
#define UNITS   4096          // 128 groups x 32 chunks

typedef unsigned long long ull;

// ---------------- device scratch (zero-initialized at module load) ---------
// inverted-order keys: larger key == smaller distance; 0 == +infinity identity
__device__ unsigned g_min1[B_ * NPTS];   // pred->tgt, low 11 bits = argmin idx
__device__ unsigned g_min2[B_ * NPTS];   // tgt->pred
__device__ float    g_part[256][6];      // per-combine-block partial sums
__device__ unsigned g_ticket;

// ---------------------------------------------------------------------------
__device__ __forceinline__ ull fma2(ull a, ull b, ull c) {
    ull d;
    asm("fma.rn.f32x2 %0, %1, %2, %3;" : "=l"(d) : "l"(a), "l"(b), "l"(c));
    return d;
}
__device__ __forceinline__ ull dup2(float x) {
    ull d;
    asm("mov.b64 %0, {%1, %1};" : "=l"(d) : "f"(x));
    return d;
}
__device__ __forceinline__ ull pk2(float a, float b) {
    ull d;
    asm("mov.b64 %0, {%1, %2};" : "=l"(d) : "f"(a), "f"(b));
    return d;
}
__device__ __forceinline__ float2 unpack2(ull v) {
    float2 r;
    asm("mov.b64 {%0, %1}, %2;" : "=f"(r.x), "=f"(r.y) : "l"(v));
    return r;
}
// order-inverting monotone encode: smaller float -> larger unsigned key
__device__ __forceinline__ unsigned encM(float f) {
    unsigned u = __float_as_uint(f);
    return ~(u ^ ((unsigned)((int)u >> 31) | 0x80000000u));
}
// inverse: key -> original float bits
__device__ __forceinline__ float decM(unsigned key, unsigned& raw) {
    unsigned enc = ~key;
    unsigned m = (enc & 0x80000000u) ? 0x80000000u : 0xFFFFFFFFu;
    raw = enc ^ m;
    return __uint_as_float(raw);
}

__device__ __forceinline__ float blockReduceSum(float v, float* sh) {
    const unsigned full = 0xffffffffu;
    #pragma unroll
    for (int o = 16; o > 0; o >>= 1) v += __shfl_down_sync(full, v, o);
    int w = threadIdx.x >> 5, l = threadIdx.x & 31;
    __syncthreads();
    if (l == 0) sh[w] = v;
    __syncthreads();
    if (threadIdx.x < 32) {
        v = (threadIdx.x < (blockDim.x >> 5)) ? sh[threadIdx.x] : 0.0f;
        #pragma unroll
        for (int o = 16; o > 0; o >>= 1) v += __shfl_down_sync(full, v, o);
    }
    return v;
}

// ---------------------------------------------------------------------------
// Persistent-wave chamfer. Work unit u in [0,4096): group g=u>>5, chunk c=u&31.
// group g: [0,64) pass1 (register=pred, chunk=target+mask, argmin embedded),
//          [64,128) pass2 (register=tgt, chunk=pred, plain min).
// g = dir*64 + b*2 + ptile. Block holds 1024 register points (4/thread) and
// accumulates mins across all its chunks of a group; one RED flush per group.
__global__ __launch_bounds__(256, 4) void chamfer_kernel(
    const float* __restrict__ preds, const float* __restrict__ target,
    const float* __restrict__ mask) {
    __shared__ ulonglong2 shA[32], shB[32];
    int k = blockIdx.x, tid = threadIdx.x;
    int u0 = (int)(((long long)k * UNITS) / GRID_CH);
    int u1 = (int)(((long long)(k + 1) * UNITS) / GRID_CH);

    int gcur = -1, bcur = 0, ptcur = 0;
    bool p1cur = true;
    ull cx[4], cy[4], cz[4];
    float bl[4], bh[4];

    for (int u = u0; u < u1; ++u) {
        int g = u >> 5, c = u & 31;
        if (g != gcur) {
            if (gcur >= 0) {
                unsigned* dst = p1cur ? g_min1 : g_min2;
                int base = bcur * NPTS + ptcur * 1024 + tid;
                #pragma unroll
                for (int i = 0; i < 4; i++)
                    atomicMax(&dst[base + i * 256], encM(fminf(bl[i], bh[i])));
            }
            gcur = g;
            p1cur = g < 64;
            int gg = p1cur ? g : g - 64;
            bcur = gg >> 1; ptcur = gg & 1;
            const float* rb = p1cur ? preds + (size_t)bcur * 5 * NPTS
                                    : target + (size_t)bcur * 4 * NPTS;
            float sgn = p1cur ? -2.f : 1.f;
            #pragma unroll
            for (int i = 0; i < 4; i++) {
                int p = ptcur * 1024 + i * 256 + tid;
                float x = rb[p], y = rb[NPTS + p], z = rb[2 * NPTS + p];
                cx[i] = dup2(sgn * x); cy[i] = dup2(sgn * y); cz[i] = dup2(sgn * z);
                bl[i] = 3.4e38f; bh[i] = 3.4e38f;
            }
        }

        __syncthreads();
        if (tid < 32) {
            int m = c * 64 + 2 * tid;
            if (p1cur) {
                const float* tb = target + (size_t)bcur * 4 * NPTS;
                float x0 = tb[m], x1 = tb[m + 1];
                float y0 = tb[NPTS + m], y1 = tb[NPTS + m + 1];
                float z0 = tb[2 * NPTS + m], z1 = tb[2 * NPTS + m + 1];
                float mk0 = mask[bcur * NPTS + m], mk1 = mask[bcur * NPTS + m + 1];
                float w0 = x0 * x0 + y0 * y0 + z0 * z0 + (mk0 == 0.f ? BIGF : 0.f);
                float w1 = x1 * x1 + y1 * y1 + z1 * z1 + (mk1 == 0.f ? BIGF : 0.f);
                shA[tid] = make_ulonglong2(pk2(x0, x1), pk2(y0, y1));
                shB[tid] = make_ulonglong2(pk2(z0, z1), pk2(w0, w1));
            } else {
                const float* pb = preds + (size_t)bcur * 5 * NPTS;
                float x0 = pb[m], x1 = pb[m + 1];
                float y0 = pb[NPTS + m], y1 = pb[NPTS + m + 1];
                float z0 = pb[2 * NPTS + m], z1 = pb[2 * NPTS + m + 1];
                float pn0 = x0 * x0 + y0 * y0 + z0 * z0;
                float pn1 = x1 * x1 + y1 * y1 + z1 * z1;
                shA[tid] = make_ulonglong2(pk2(-2.f * x0, -2.f * x1),
                                           pk2(-2.f * y0, -2.f * y1));
                shB[tid] = make_ulonglong2(pk2(-2.f * z0, -2.f * z1),
                                           pk2(pn0, pn1));
            }
        }
        __syncthreads();

        if (p1cur) {
            unsigned jlo = (unsigned)(c * 64);
            #pragma unroll 4
            for (int j = 0; j < 32; j++) {
                ulonglong2 A = shA[j], Bv = shB[j];
                unsigned jhi = jlo | 1u;
                #pragma unroll
                for (int i = 0; i < 4; i++) {
                    ull t = fma2(cz[i], Bv.x, Bv.y);
                    t = fma2(cy[i], A.y, t);
                    t = fma2(cx[i], A.x, t);
                    float2 v = unpack2(t);
                    unsigned elo = (__float_as_uint(v.x) & 0xFFFFF800u) | jlo;
                    unsigned ehi = (__float_as_uint(v.y) & 0xFFFFF800u) | jhi;
                    bl[i] = fminf(bl[i], __uint_as_float(elo));
                    bh[i] = fminf(bh[i], __uint_as_float(ehi));
                }
                jlo += 2;
            }
        } else {
            #pragma unroll 4
            for (int j = 0; j < 32; j++) {
                ulonglong2 A = shA[j], Bv = shB[j];
                #pragma unroll
                for (int i = 0; i < 4; i++) {
                    ull t = fma2(cz[i], Bv.x, Bv.y);
                    t = fma2(cy[i], A.y, t);
                    t = fma2(cx[i], A.x, t);
                    float2 v = unpack2(t);
                    bl[i] = fminf(bl[i], v.x);
                    bh[i] = fminf(bh[i], v.y);
                }
            }
        }
    }
    if (gcur >= 0) {
        unsigned* dst = p1cur ? g_min1 : g_min2;
        int base = bcur * NPTS + ptcur * 1024 + tid;
        #pragma unroll
        for (int i = 0; i < 4; i++)
            atomicMax(&dst[base + i * 256], encM(fminf(bl[i], bh[i])));
    }
}

// ---------------------------------------------------------------------------
// Combine + all cheap reductions + final. 256 blocks:
//   [0,128)  pred side: minD_pred, |dE|, entropy, nhp, teh (+kld slice)
//   [128,256) tgt side: minD_tgt*mask, nht
// Partials in g_part (race-free slots); ticketed last block finalizes.
__global__ __launch_bounds__(256) void combine_kernel(
    const float* __restrict__ preds, const float* __restrict__ target,
    const float* __restrict__ mask,  const float* __restrict__ mu,
    const float* __restrict__ logvar, const float* __restrict__ e_init,
    const float* __restrict__ kl_weight, float* __restrict__ out, int out_size) {
    __shared__ float shr[8];
    __shared__ int s_last;
    int blk = blockIdx.x, tid = threadIdx.x;

    if (blk < 128) {
        int b = blk >> 2, seg = blk & 3;
        const float* pb = preds + (size_t)b * 5 * NPTS;
        const float* tE = target + (size_t)b * 4 * NPTS + 3 * NPTS;
        float md = 0.f, le = 0.f, ent = 0.f, nhp = 0.f, teh = 0.f;
        #pragma unroll
        for (int r = 0; r < 2; r++) {
            int n = seg * 512 + r * 256 + tid;
            int gidx = b * NPTS + n;
            unsigned raw;
            float best = decM(g_min1[gidx], raw);
            g_min1[gidx] = 0u;
            int idx = (int)(raw & 0x7FFu);
            float x = pb[n], y = pb[NPTS + n], z = pb[2 * NPTS + n];
            float pn = x * x + y * y + z * z;
            md += fmaxf(pn + best, 0.f);
            float pE = pb[3 * NPTS + n], h = pb[4 * NPTS + n];
            le += fabsf(pE - tE[idx]);
            ent += -(h * __logf(h + EPSF) + (1.f - h) * __logf(1.f - h + EPSF));
            nhp += h;
            teh += pE * h;
        }
        float kld = 0.f;
        if (tid < 64) {
            int ki = blk * 64 + tid;   // flattened [B_*L_] = 8192
            float m_ = mu[ki], lv = logvar[ki];
            kld = 1.f + lv - m_ * m_ - __expf(lv);
        }
        md  = blockReduceSum(md, shr);
        le  = blockReduceSum(le, shr);
        ent = blockReduceSum(ent, shr);
        kld = blockReduceSum(kld, shr);
        nhp = blockReduceSum(nhp, shr);
        teh = blockReduceSum(teh, shr);
        if (tid == 0) {
            float* s = g_part[blk];
            s[0] = md; s[1] = le; s[2] = ent; s[3] = kld; s[4] = nhp; s[5] = teh;
        }
    } else {
        int w = blk - 128;
        int b = w >> 2, seg = w & 3;
        const float* tb = target + (size_t)b * 4 * NPTS;
        float s = 0.f, nht = 0.f;
        #pragma unroll
        for (int r = 0; r < 2; r++) {
            int m = seg * 512 + r * 256 + tid;
            int gidx = b * NPTS + m;
            unsigned raw;
            float best = decM(g_min2[gidx], raw);
            g_min2[gidx] = 0u;
            float x = tb[m], y = tb[NPTS + m], z = tb[2 * NPTS + m];
            float tn = x * x + y * y + z * z;
            float mk = mask[gidx];
            s += fmaxf(tn + best, 0.f) * mk;
            nht += mk;
        }
        s   = blockReduceSum(s, shr);
        nht = blockReduceSum(nht, shr);
        if (tid == 0) {
            float* p = g_part[blk];
            p[0] = s; p[1] = nht;
        }
    }

    if (tid == 0) {
        __threadfence();
        unsigned t = atomicAdd(&g_ticket, 1u);
        s_last = (t == 255u);
    }
    __syncthreads();
    if (!s_last) return;

    // ---- last block: aggregate 256 slots + finalize ----
    float vMD = blockReduceSum(tid < 128 ? g_part[tid][0] : 0.f, shr);
    float vLE = blockReduceSum(tid < 128 ? g_part[tid][1] : 0.f, shr);
    float vEN = blockReduceSum(tid < 128 ? g_part[tid][2] : 0.f, shr);
    float vKL = blockReduceSum(tid < 128 ? g_part[tid][3] : 0.f, shr);
    float vS  = blockReduceSum(tid >= 128 ? g_part[tid][0] : 0.f, shr);
    float vNH = blockReduceSum(tid >= 128 ? g_part[tid][1] : 0.f, shr);

    float dh2 = 0.f, de2 = 0.f;
    if (tid < B_) {
        float nhp = 0.f, teh = 0.f, nht = 0.f;
        #pragma unroll
        for (int s2 = 0; s2 < 4; s2++) {
            nhp += g_part[4 * tid + s2][4];
            teh += g_part[4 * tid + s2][5];
            nht += g_part[128 + 4 * tid + s2][1];
        }
        float dh = nhp - nht;
        float de = teh - e_init[tid];
        dh2 = dh * dh; de2 = de * de;
    }
    if (tid < 32) {
        const unsigned full = 0xffffffffu;
        #pragma unroll
        for (int o = 16; o > 0; o >>= 1) {
            dh2 += __shfl_down_sync(full, dh2, o);
            de2 += __shfl_down_sync(full, de2, o);
        }
    }
    if (tid == 0) {
        float chamP = vMD / (float)(B_ * NPTS);
        float chamT = vS / vNH;
        float loss_chamf = (chamT + chamP) * LAMBDA_CHAMFER;
        float localE = vLE / (float)(B_ * NPTS);
        float ge   = LAMBDA_E_SUM * de2 / (float)B_;
        float hit  = LAMBDA_HIT   * dh2 / (float)B_;
        float entr = LAMBDA_HIT_ENTROPY * vEN / (float)(B_ * NPTS);
        float kl   = kl_weight[0] * (-0.5f * vKL / (float)B_);
        float total = loss_chamf + localE + kl + ge + hit + entr;

        if (out_size >= 6) {
            out[0] = total;
            out[1] = loss_chamf;
            out[2] = localE;
            out[3] = ge;
            out[4] = hit;
            out[5] = kl;
        } else if (out_size == 5) {
            out[0] = loss_chamf; out[1] = localE; out[2] = ge;
            out[3] = hit;        out[4] = kl;
        } else {
            out[0] = total;
        }
        g_ticket = 0u;   // reset for next graph replay
    }
}

// ---------------------------------------------------------------------------
extern "C" void kernel_launch(void* const* d_in, const int* in_sizes, int n_in,
                              void* d_out, int out_size) {
    const float* preds  = (const float*)d_in[0];
    const float* target = (const float*)d_in[1];
    const float* tmask  = (const float*)d_in[2];
    const float* mu     = (const float*)d_in[3];
    const float* logvar = (const float*)d_in[4];
    const float* e_init = (const float*)d_in[5];
    const float* klw    = (const float*)d_in[6];
    float* out = (float*)d_out;

    chamfer_kernel<<<GRID_CH, 256>>>(preds, target, tmask);
    combine_kernel<<<256, 256>>>(preds, target, tmask, mu, logvar,
                                 e_init, klw, out, out_size);
}